// round 1
// baseline (speedup 1.0000x reference)
#include <cuda_runtime.h>

#define NN 100000
#define EE 1000000
#define GG 2000
#define NDIM 64
#define EDIM 16
#define LAYERS 4

// Scratch (device globals; no allocation allowed)
__device__ float g_buf0[NN * NDIM];
__device__ float g_buf1[NN * NDIM];
__device__ float g_aggr[NN * NDIM];
__device__ float g_sums[GG * NDIM];
__device__ float g_cnts[GG];

typedef unsigned long long ull;

__device__ __forceinline__ ull pack2(float a, float b) {
    ull r;
    asm("mov.b64 %0, {%1,%2};" : "=l"(r) : "f"(a), "f"(b));
    return r;
}
__device__ __forceinline__ void unpack2(ull v, float& a, float& b) {
    asm("mov.b64 {%0,%1}, %2;" : "=f"(a), "=f"(b) : "l"(v));
}
// Packed dual-fp32 FMA (Blackwell f32x2 pipe): d = a*b + d
__device__ __forceinline__ void ffma2(ull& d, ull a, ull b) {
    asm("fma.rn.f32x2 %0, %1, %2, %0;" : "+l"(d) : "l"(a), "l"(b));
}
// Vector atomic add, 4 floats (sm_90+)
__device__ __forceinline__ void red4(float* p, float x, float y, float z, float w) {
    asm volatile("red.global.add.v4.f32 [%0], {%1,%2,%3,%4};"
                 :: "l"(p), "f"(x), "f"(y), "f"(z), "f"(w) : "memory");
}

// ============================================================================
// Edge kernel: for each edge e: m = relu(x[src] + edge_attr[e] @ lin_e)
//              aggr[dst] += m   (vector atomics)
// 16 threads per edge; each thread owns 4 output dims; lin_e in registers.
// ============================================================================
__global__ void __launch_bounds__(256) edge_kernel(
    const float* __restrict__ x, const int* __restrict__ ei,
    const float* __restrict__ ea, const float* __restrict__ lin,
    float* __restrict__ aggr)
{
    const int lane16 = threadIdx.x & 15;
    const int half   = (threadIdx.x >> 4) & 1;

    // Per-thread weight slice: lin[k][lane16*4 .. +3], k = 0..15  (64 regs)
    ull wA[16], wB[16];
#pragma unroll
    for (int k = 0; k < 16; k++) {
        float4 w = *(const float4*)(lin + k * NDIM + lane16 * 4);
        wA[k] = pack2(w.x, w.y);
        wB[k] = pack2(w.z, w.w);
    }

    const int warp   = (blockIdx.x * blockDim.x + threadIdx.x) >> 5;
    const int nwarps = (gridDim.x * blockDim.x) >> 5;

    // Warp-uniform loop over edge pairs so __shfl masks stay full.
    for (int base = warp * 2; base < EE; base += nwarps * 2) {
        int e = base + half;
        bool valid = (e < EE);
        int er = valid ? e : base;   // safe address for predicated-off half

        float eav = ea[(size_t)er * EDIM + lane16];
        int src = ei[er];
        int dst = ei[EE + er];

        float4 xv = *(const float4*)(x + (size_t)src * NDIM + lane16 * 4);
        ull accA = pack2(xv.x, xv.y);
        ull accB = pack2(xv.z, xv.w);

#pragma unroll
        for (int k = 0; k < 16; k++) {
            float a = __shfl_sync(0xFFFFFFFFu, eav, k, 16);
            ull aa = pack2(a, a);
            ffma2(accA, aa, wA[k]);
            ffma2(accB, aa, wB[k]);
        }

        float m0, m1, m2, m3;
        unpack2(accA, m0, m1);
        unpack2(accB, m2, m3);
        m0 = fmaxf(m0, 0.f); m1 = fmaxf(m1, 0.f);
        m2 = fmaxf(m2, 0.f); m3 = fmaxf(m3, 0.f);

        if (valid)
            red4(aggr + (size_t)dst * NDIM + lane16 * 4, m0, m1, m2, m3);
    }
}

// ============================================================================
// Node kernel: h = (1+eps)*x + aggr
//              x_out = relu( relu(h@W1 + b1) @ W2 + b2 )
// Warp handles 4 nodes; lane owns dims (lane, lane+32) packed f32x2.
// Weights in shared as interleaved (d, d+32) pairs.
// ============================================================================
__global__ void __launch_bounds__(256) node_kernel(
    const float* __restrict__ xin, const float* __restrict__ aggr,
    const float* __restrict__ W1, const float* __restrict__ b1,
    const float* __restrict__ W2, const float* __restrict__ b2,
    const float* __restrict__ epsp, int l,
    float* __restrict__ xout)
{
    __shared__ ull W1s[64 * 32];
    __shared__ ull W2s[64 * 32];
    for (int i = threadIdx.x; i < 64 * 32; i += blockDim.x) {
        int k = i >> 5, d = i & 31;
        W1s[i] = pack2(W1[k * 64 + d], W1[k * 64 + d + 32]);
        W2s[i] = pack2(W2[k * 64 + d], W2[k * 64 + d + 32]);
    }
    __syncthreads();

    const float epsv = 1.0f + epsp[l];
    const int lane = threadIdx.x & 31;
    const ull b1p = pack2(b1[lane], b1[lane + 32]);
    const ull b2p = pack2(b2[lane], b2[lane + 32]);

    const int warp   = (blockIdx.x * blockDim.x + threadIdx.x) >> 5;
    const int nwarps = (gridDim.x * blockDim.x) >> 5;

    for (int n0 = warp * 4; n0 < NN; n0 += nwarps * 4) {   // NN % 4 == 0
        float h0[4], h1[4];
#pragma unroll
        for (int j = 0; j < 4; j++) {
            size_t off = (size_t)(n0 + j) * NDIM + lane;
            h0[j] = fmaf(epsv, xin[off],      aggr[off]);
            h1[j] = fmaf(epsv, xin[off + 32], aggr[off + 32]);
        }

        // ---- matmul 1 ----
        ull acc[4] = {b1p, b1p, b1p, b1p};
#pragma unroll 8
        for (int k = 0; k < 32; k++) {
            ull w = W1s[k * 32 + lane];
#pragma unroll
            for (int j = 0; j < 4; j++) {
                float a = __shfl_sync(0xFFFFFFFFu, h0[j], k);
                ffma2(acc[j], pack2(a, a), w);
            }
        }
#pragma unroll 8
        for (int k = 0; k < 32; k++) {
            ull w = W1s[(k + 32) * 32 + lane];
#pragma unroll
            for (int j = 0; j < 4; j++) {
                float a = __shfl_sync(0xFFFFFFFFu, h1[j], k);
                ffma2(acc[j], pack2(a, a), w);
            }
        }
#pragma unroll
        for (int j = 0; j < 4; j++) {
            float y0, y1;
            unpack2(acc[j], y0, y1);
            h0[j] = fmaxf(y0, 0.f);
            h1[j] = fmaxf(y1, 0.f);
            acc[j] = b2p;
        }

        // ---- matmul 2 ----
#pragma unroll 8
        for (int k = 0; k < 32; k++) {
            ull w = W2s[k * 32 + lane];
#pragma unroll
            for (int j = 0; j < 4; j++) {
                float a = __shfl_sync(0xFFFFFFFFu, h0[j], k);
                ffma2(acc[j], pack2(a, a), w);
            }
        }
#pragma unroll 8
        for (int k = 0; k < 32; k++) {
            ull w = W2s[(k + 32) * 32 + lane];
#pragma unroll
            for (int j = 0; j < 4; j++) {
                float a = __shfl_sync(0xFFFFFFFFu, h1[j], k);
                ffma2(acc[j], pack2(a, a), w);
            }
        }

#pragma unroll
        for (int j = 0; j < 4; j++) {
            float y0, y1;
            unpack2(acc[j], y0, y1);
            size_t off = (size_t)(n0 + j) * NDIM + lane;
            xout[off]      = fmaxf(y0, 0.f);
            xout[off + 32] = fmaxf(y1, 0.f);
        }
    }
}

// ============================================================================
// Pool: sums[batch[n]] += x[n], cnts[batch[n]] += 1
// ============================================================================
__global__ void __launch_bounds__(256) pool_kernel(
    const float* __restrict__ x, const int* __restrict__ batch,
    float* __restrict__ sums, float* __restrict__ cnts)
{
    const int lane16 = threadIdx.x & 15;
    const int half   = (threadIdx.x >> 4) & 1;
    const int warp   = (blockIdx.x * blockDim.x + threadIdx.x) >> 5;
    const int nwarps = (gridDim.x * blockDim.x) >> 5;

    for (int base = warp * 2; base < NN; base += nwarps * 2) {
        int n = base + half;          // NN even, stride even -> always < NN
        int g = batch[n];
        float4 v = *(const float4*)(x + (size_t)n * NDIM + lane16 * 4);
        red4(sums + (size_t)g * NDIM + lane16 * 4, v.x, v.y, v.z, v.w);
        if (lane16 == 0) atomicAdd(cnts + g, 1.0f);
    }
}

// ============================================================================
// Head: pooled = sums/max(cnt,1); h=[pooled, t]; out = relu(h@hW1+hb1)@hW2+hb2
// Warp per graph.
// ============================================================================
__global__ void __launch_bounds__(256) head_kernel(
    const float* __restrict__ sums, const float* __restrict__ cnts,
    const float* __restrict__ t_cond,
    const float* __restrict__ hW1, const float* __restrict__ hb1,
    const float* __restrict__ hW2, const float* __restrict__ hb2,
    float* __restrict__ out)
{
    const int lane = threadIdx.x & 31;
    const int g    = (blockIdx.x * blockDim.x + threadIdx.x) >> 5;
    if (g >= GG) return;

    float c  = fmaxf(cnts[g], 1.0f);
    float p0 = sums[(size_t)g * NDIM + lane] / c;
    float p1 = sums[(size_t)g * NDIM + lane + 32] / c;

    float acc0 = hb1[lane], acc1 = hb1[lane + 32];
    for (int k = 0; k < 32; k++) {
        float a = __shfl_sync(0xFFFFFFFFu, p0, k);
        acc0 = fmaf(a, hW1[k * 64 + lane],      acc0);
        acc1 = fmaf(a, hW1[k * 64 + lane + 32], acc1);
    }
    for (int k = 0; k < 32; k++) {
        float a = __shfl_sync(0xFFFFFFFFu, p1, k);
        acc0 = fmaf(a, hW1[(k + 32) * 64 + lane],      acc0);
        acc1 = fmaf(a, hW1[(k + 32) * 64 + lane + 32], acc1);
    }
    float t = t_cond[g];
    acc0 = fmaf(t, hW1[64 * 64 + lane],      acc0);
    acc1 = fmaf(t, hW1[64 * 64 + lane + 32], acc1);

    acc0 = fmaxf(acc0, 0.f);
    acc1 = fmaxf(acc1, 0.f);

    float r = acc0 * hW2[lane] + acc1 * hW2[lane + 32];
#pragma unroll
    for (int o = 16; o; o >>= 1) r += __shfl_xor_sync(0xFFFFFFFFu, r, o);
    if (lane == 0) out[g] = r + hb2[0];
}

// ============================================================================
extern "C" void kernel_launch(void* const* d_in, const int* in_sizes, int n_in,
                              void* d_out, int out_size)
{
    const float* x      = (const float*)d_in[0];
    const int*   ei     = (const int*)  d_in[1];
    const float* ea     = (const float*)d_in[2];
    const int*   batch  = (const int*)  d_in[3];
    const float* t_cond = (const float*)d_in[4];
    const float* lin_e  = (const float*)d_in[5];
    const float* W1     = (const float*)d_in[6];
    const float* b1     = (const float*)d_in[7];
    const float* W2     = (const float*)d_in[8];
    const float* b2     = (const float*)d_in[9];
    const float* eps    = (const float*)d_in[10];
    const float* hW1    = (const float*)d_in[11];
    const float* hb1    = (const float*)d_in[12];
    const float* hW2    = (const float*)d_in[13];
    const float* hb2    = (const float*)d_in[14];
    float* out = (float*)d_out;

    float *buf0, *buf1, *aggr, *sums, *cnts;
    cudaGetSymbolAddress((void**)&buf0, g_buf0);
    cudaGetSymbolAddress((void**)&buf1, g_buf1);
    cudaGetSymbolAddress((void**)&aggr, g_aggr);
    cudaGetSymbolAddress((void**)&sums, g_sums);
    cudaGetSymbolAddress((void**)&cnts, g_cnts);

    float* bufs[2] = {buf0, buf1};
    const float* cur = x;
    for (int l = 0; l < LAYERS; l++) {
        cudaMemsetAsync(aggr, 0, sizeof(float) * NN * NDIM, 0);
        edge_kernel<<<1024, 256>>>(cur, ei, ea, lin_e + (size_t)l * EDIM * NDIM, aggr);
        float* nxt = bufs[l & 1];
        node_kernel<<<1184, 256>>>(cur, aggr,
                                   W1 + (size_t)l * 64 * 64, b1 + (size_t)l * 64,
                                   W2 + (size_t)l * 64 * 64, b2 + (size_t)l * 64,
                                   eps, l, nxt);
        cur = nxt;
    }
    cudaMemsetAsync(sums, 0, sizeof(float) * GG * NDIM, 0);
    cudaMemsetAsync(cnts, 0, sizeof(float) * GG, 0);
    pool_kernel<<<512, 256>>>(cur, batch, sums, cnts);
    head_kernel<<<(GG + 7) / 8, 256>>>(sums, cnts, t_cond, hW1, hb1, hW2, hb2, out);
}

// round 2
// speedup vs baseline: 1.3557x; 1.3557x over previous
#include <cuda_runtime.h>

#define NN 100000
#define EE 1000000
#define GG 2000

// ---------------- scratch (device globals; no allocation allowed) ----------
__device__ float g_buf0[NN * 64];
__device__ float g_buf1[NN * 64];
__device__ int   g_rowptr[NN + 1];
__device__ int   g_cnt[NN];
__device__ int   g_cursor[NN];
__device__ int   g_srcperm[EE];
__device__ int   g_eid[EE];
__device__ float g_eaperm[EE * 16];
__device__ float g_sums[GG * 64];
__device__ float g_cnts[GG];

typedef unsigned long long ull;

__device__ __forceinline__ ull pack2(float a, float b) {
    ull r; asm("mov.b64 %0, {%1,%2};" : "=l"(r) : "f"(a), "f"(b)); return r;
}
__device__ __forceinline__ void unpack2(ull v, float& a, float& b) {
    asm("mov.b64 {%0,%1}, %2;" : "=f"(a), "=f"(b) : "l"(v));
}
__device__ __forceinline__ void ffma2(ull& d, ull a, ull b) {
    asm("fma.rn.f32x2 %0, %1, %2, %0;" : "+l"(d) : "l"(a), "l"(b));
}
__device__ __forceinline__ ull add2(ull a, ull b) {
    ull r; asm("add.rn.f32x2 %0, %1, %2;" : "=l"(r) : "l"(a), "l"(b)); return r;
}
__device__ __forceinline__ void red2(float* p, float x, float y) {
    asm volatile("red.global.add.v2.f32 [%0], {%1,%2};"
                 :: "l"(p), "f"(x), "f"(y) : "memory");
}

// ============================ CSR build =====================================
__global__ void __launch_bounds__(256) count_kernel(const int* __restrict__ ei,
                                                    int* __restrict__ cnt) {
    int e = blockIdx.x * blockDim.x + threadIdx.x;
    if (e < EE) atomicAdd(&cnt[ei[EE + e]], 1);
}

// Single-block exclusive scan over NN counts -> rowptr[NN+1]
__global__ void __launch_bounds__(1024) scan_kernel(const int* __restrict__ cnt,
                                                    int* __restrict__ rowptr) {
    const int CH = (NN + 1023) / 1024;  // 98
    int tid = threadIdx.x;
    int base = tid * CH;
    int s = 0;
    for (int i = 0; i < CH; i++) {
        int idx = base + i;
        if (idx < NN) s += cnt[idx];
    }
    __shared__ int sh[1024];
    sh[tid] = s;
    __syncthreads();
    for (int off = 1; off < 1024; off <<= 1) {
        int v = (tid >= off) ? sh[tid - off] : 0;
        __syncthreads();
        sh[tid] += v;
        __syncthreads();
    }
    int run = sh[tid] - s;  // exclusive prefix of this chunk
    for (int i = 0; i < CH; i++) {
        int idx = base + i;
        if (idx < NN) { rowptr[idx] = run; run += cnt[idx]; }
    }
    if (NN >= base && NN < base + CH) rowptr[NN] = run;
}

__global__ void __launch_bounds__(256) scatter_kernel(const int* __restrict__ ei,
                                                      int* __restrict__ cursor,
                                                      int* __restrict__ srcperm,
                                                      int* __restrict__ eid) {
    int e = blockIdx.x * blockDim.x + threadIdx.x;
    if (e < EE) {
        int d = ei[EE + e];
        int pos = atomicAdd(&cursor[d], 1);
        srcperm[pos] = ei[e];
        eid[pos] = e;
    }
}

__global__ void __launch_bounds__(256) permute_ea_kernel(const float* __restrict__ ea,
                                                         const int* __restrict__ eid,
                                                         float* __restrict__ eaperm) {
    int idx = blockIdx.x * blockDim.x + threadIdx.x;  // over EE*4 float4 chunks
    if (idx < EE * 4) {
        int j = idx >> 2, c = idx & 3;
        ((float4*)eaperm)[(size_t)j * 4 + c] =
            ((const float4*)ea)[(size_t)eid[j] * 4 + c];
    }
}

// ============================ fused layer ===================================
// Per node n:
//   aggr = sum over in-edges p: relu( x[src[p]] + ea[p] @ lin_e )
//   h    = (1+eps)*x[n] + aggr
//   y    = relu( relu(h@W1+b1) @ W2 + b2 )
// Lane owns dims (2*lane, 2*lane+1) packed f32x2. Warp handles 4 nodes.
// LAST layer: fuse mean-pool accumulation instead of writing x.
template <bool LAST>
__global__ void __launch_bounds__(256) layer_kernel(
    const float* __restrict__ x,
    const int* __restrict__ rowptr, const int* __restrict__ srcperm,
    const float* __restrict__ eaperm,
    const float* __restrict__ line,
    const float* __restrict__ W1, const float* __restrict__ b1,
    const float* __restrict__ W2, const float* __restrict__ b2,
    const float* __restrict__ epsp, int l,
    float* __restrict__ xout,
    const int* __restrict__ batch,
    float* __restrict__ sums, float* __restrict__ cnts)
{
    __shared__ ull W1s[64 * 32];
    __shared__ ull W2s[64 * 32];
    for (int i = threadIdx.x; i < 64 * 32; i += 256) {
        int k = i >> 5, d2 = (i & 31) * 2;
        W1s[i] = pack2(W1[k * 64 + d2], W1[k * 64 + d2 + 1]);
        W2s[i] = pack2(W2[k * 64 + d2], W2[k * 64 + d2 + 1]);
    }
    __syncthreads();

    const int lane = threadIdx.x & 31;

    // Edge-transform weights in registers: lin_e[k][2*lane .. +1], k=0..15
    ull w[16];
#pragma unroll
    for (int k = 0; k < 16; k++) {
        float2 wv = *(const float2*)(line + k * 64 + lane * 2);
        w[k] = pack2(wv.x, wv.y);
    }

    const float epsv = 1.0f + epsp[l];
    const ull b1p = pack2(b1[lane * 2], b1[lane * 2 + 1]);
    const ull b2p = pack2(b2[lane * 2], b2[lane * 2 + 1]);

    const int warp = (blockIdx.x * 256 + threadIdx.x) >> 5;
    const int n0 = warp * 4;  // grid sized so n0+3 < NN always

    float h0[4], h1[4];
#pragma unroll
    for (int j = 0; j < 4; j++) {
        const int n = n0 + j;
        float a0 = 0.f, a1 = 0.f;
        const int p0 = rowptr[n], p1 = rowptr[n + 1];
#pragma unroll 2
        for (int p = p0; p < p1; p++) {
            int s = srcperm[p];
            float2 xv = *(const float2*)(x + (size_t)s * 64 + lane * 2);
            const float4* eap = (const float4*)(eaperm + (size_t)p * 16);
            float4 q0 = eap[0], q1 = eap[1], q2 = eap[2], q3 = eap[3];
            ull eA = pack2(xv.x, xv.y);
            ull eB = pack2(0.f, 0.f);
            ffma2(eA, pack2(q0.x, q0.x), w[0]);
            ffma2(eB, pack2(q0.y, q0.y), w[1]);
            ffma2(eA, pack2(q0.z, q0.z), w[2]);
            ffma2(eB, pack2(q0.w, q0.w), w[3]);
            ffma2(eA, pack2(q1.x, q1.x), w[4]);
            ffma2(eB, pack2(q1.y, q1.y), w[5]);
            ffma2(eA, pack2(q1.z, q1.z), w[6]);
            ffma2(eB, pack2(q1.w, q1.w), w[7]);
            ffma2(eA, pack2(q2.x, q2.x), w[8]);
            ffma2(eB, pack2(q2.y, q2.y), w[9]);
            ffma2(eA, pack2(q2.z, q2.z), w[10]);
            ffma2(eB, pack2(q2.w, q2.w), w[11]);
            ffma2(eA, pack2(q3.x, q3.x), w[12]);
            ffma2(eB, pack2(q3.y, q3.y), w[13]);
            ffma2(eA, pack2(q3.z, q3.z), w[14]);
            ffma2(eB, pack2(q3.w, q3.w), w[15]);
            ull es = add2(eA, eB);
            float m0, m1;
            unpack2(es, m0, m1);
            a0 += fmaxf(m0, 0.f);
            a1 += fmaxf(m1, 0.f);
        }
        float2 xs = *(const float2*)(x + (size_t)n * 64 + lane * 2);
        h0[j] = fmaf(epsv, xs.x, a0);
        h1[j] = fmaf(epsv, xs.y, a1);
    }

    // ---- MLP matmul 1 ----
    ull acc[4] = {b1p, b1p, b1p, b1p};
#pragma unroll 8
    for (int kk = 0; kk < 32; kk++) {
        ull wa = W1s[(2 * kk) * 32 + lane];
        ull wb = W1s[(2 * kk + 1) * 32 + lane];
#pragma unroll
        for (int j = 0; j < 4; j++) {
            float a = __shfl_sync(0xFFFFFFFFu, h0[j], kk);
            float b = __shfl_sync(0xFFFFFFFFu, h1[j], kk);
            ffma2(acc[j], pack2(a, a), wa);
            ffma2(acc[j], pack2(b, b), wb);
        }
    }
#pragma unroll
    for (int j = 0; j < 4; j++) {
        float y0, y1;
        unpack2(acc[j], y0, y1);
        h0[j] = fmaxf(y0, 0.f);
        h1[j] = fmaxf(y1, 0.f);
        acc[j] = b2p;
    }

    // ---- MLP matmul 2 ----
#pragma unroll 8
    for (int kk = 0; kk < 32; kk++) {
        ull wa = W2s[(2 * kk) * 32 + lane];
        ull wb = W2s[(2 * kk + 1) * 32 + lane];
#pragma unroll
        for (int j = 0; j < 4; j++) {
            float a = __shfl_sync(0xFFFFFFFFu, h0[j], kk);
            float b = __shfl_sync(0xFFFFFFFFu, h1[j], kk);
            ffma2(acc[j], pack2(a, a), wa);
            ffma2(acc[j], pack2(b, b), wb);
        }
    }

#pragma unroll
    for (int j = 0; j < 4; j++) {
        float y0, y1;
        unpack2(acc[j], y0, y1);
        y0 = fmaxf(y0, 0.f);
        y1 = fmaxf(y1, 0.f);
        if (!LAST) {
            *(float2*)(xout + (size_t)(n0 + j) * 64 + lane * 2) = make_float2(y0, y1);
        } else {
            int g = batch[n0 + j];
            red2(sums + (size_t)g * 64 + lane * 2, y0, y1);
            if (lane == 0) atomicAdd(cnts + g, 1.0f);
        }
    }
}

// ============================ head ==========================================
__global__ void __launch_bounds__(256) head_kernel(
    const float* __restrict__ sums, const float* __restrict__ cnts,
    const float* __restrict__ t_cond,
    const float* __restrict__ hW1, const float* __restrict__ hb1,
    const float* __restrict__ hW2, const float* __restrict__ hb2,
    float* __restrict__ out)
{
    const int lane = threadIdx.x & 31;
    const int g    = (blockIdx.x * blockDim.x + threadIdx.x) >> 5;
    if (g >= GG) return;

    float c  = fmaxf(cnts[g], 1.0f);
    float p0 = sums[(size_t)g * 64 + lane] / c;
    float p1 = sums[(size_t)g * 64 + lane + 32] / c;

    float acc0 = hb1[lane], acc1 = hb1[lane + 32];
    for (int k = 0; k < 32; k++) {
        float a = __shfl_sync(0xFFFFFFFFu, p0, k);
        acc0 = fmaf(a, hW1[k * 64 + lane],      acc0);
        acc1 = fmaf(a, hW1[k * 64 + lane + 32], acc1);
    }
    for (int k = 0; k < 32; k++) {
        float a = __shfl_sync(0xFFFFFFFFu, p1, k);
        acc0 = fmaf(a, hW1[(k + 32) * 64 + lane],      acc0);
        acc1 = fmaf(a, hW1[(k + 32) * 64 + lane + 32], acc1);
    }
    float t = t_cond[g];
    acc0 = fmaf(t, hW1[64 * 64 + lane],      acc0);
    acc1 = fmaf(t, hW1[64 * 64 + lane + 32], acc1);

    acc0 = fmaxf(acc0, 0.f);
    acc1 = fmaxf(acc1, 0.f);

    float r = acc0 * hW2[lane] + acc1 * hW2[lane + 32];
#pragma unroll
    for (int o = 16; o; o >>= 1) r += __shfl_xor_sync(0xFFFFFFFFu, r, o);
    if (lane == 0) out[g] = r + hb2[0];
}

// ============================================================================
extern "C" void kernel_launch(void* const* d_in, const int* in_sizes, int n_in,
                              void* d_out, int out_size)
{
    const float* x      = (const float*)d_in[0];
    const int*   ei     = (const int*)  d_in[1];
    const float* ea     = (const float*)d_in[2];
    const int*   batch  = (const int*)  d_in[3];
    const float* t_cond = (const float*)d_in[4];
    const float* lin_e  = (const float*)d_in[5];
    const float* W1     = (const float*)d_in[6];
    const float* b1     = (const float*)d_in[7];
    const float* W2     = (const float*)d_in[8];
    const float* b2     = (const float*)d_in[9];
    const float* eps    = (const float*)d_in[10];
    const float* hW1    = (const float*)d_in[11];
    const float* hb1    = (const float*)d_in[12];
    const float* hW2    = (const float*)d_in[13];
    const float* hb2    = (const float*)d_in[14];
    float* out = (float*)d_out;

    float *buf0, *buf1, *eaperm, *sums, *cnts;
    int *rowptr, *cnt, *cursor, *srcperm, *eid;
    cudaGetSymbolAddress((void**)&buf0, g_buf0);
    cudaGetSymbolAddress((void**)&buf1, g_buf1);
    cudaGetSymbolAddress((void**)&rowptr, g_rowptr);
    cudaGetSymbolAddress((void**)&cnt, g_cnt);
    cudaGetSymbolAddress((void**)&cursor, g_cursor);
    cudaGetSymbolAddress((void**)&srcperm, g_srcperm);
    cudaGetSymbolAddress((void**)&eid, g_eid);
    cudaGetSymbolAddress((void**)&eaperm, g_eaperm);
    cudaGetSymbolAddress((void**)&sums, g_sums);
    cudaGetSymbolAddress((void**)&cnts, g_cnts);

    // ---- CSR build (once per launch) ----
    cudaMemsetAsync(cnt, 0, sizeof(int) * NN, 0);
    count_kernel<<<(EE + 255) / 256, 256>>>(ei, cnt);
    scan_kernel<<<1, 1024>>>(cnt, rowptr);
    cudaMemcpyAsync(cursor, rowptr, sizeof(int) * NN, cudaMemcpyDeviceToDevice, 0);
    scatter_kernel<<<(EE + 255) / 256, 256>>>(ei, cursor, srcperm, eid);
    permute_ea_kernel<<<(EE * 4 + 255) / 256, 256>>>(ea, eid, eaperm);

    // ---- pooled accumulators ----
    cudaMemsetAsync(sums, 0, sizeof(float) * GG * 64, 0);
    cudaMemsetAsync(cnts, 0, sizeof(float) * GG, 0);

    // ---- 4 fused layers ----
    const int blocks = (NN / 4 + 7) / 8;  // 4 nodes/warp, 8 warps/block = 3125
    float* bufs[2] = {buf0, buf1};
    const float* cur = x;
    for (int l = 0; l < 3; l++) {
        float* nxt = bufs[l & 1];
        layer_kernel<false><<<blocks, 256>>>(
            cur, rowptr, srcperm, eaperm,
            lin_e + (size_t)l * 16 * 64,
            W1 + (size_t)l * 64 * 64, b1 + (size_t)l * 64,
            W2 + (size_t)l * 64 * 64, b2 + (size_t)l * 64,
            eps, l, nxt, batch, sums, cnts);
        cur = nxt;
    }
    layer_kernel<true><<<blocks, 256>>>(
        cur, rowptr, srcperm, eaperm,
        lin_e + (size_t)3 * 16 * 64,
        W1 + (size_t)3 * 64 * 64, b1 + (size_t)3 * 64,
        W2 + (size_t)3 * 64 * 64, b2 + (size_t)3 * 64,
        eps, 3, nullptr, batch, sums, cnts);

    head_kernel<<<(GG + 7) / 8, 256>>>(sums, cnts, t_cond, hW1, hb1, hW2, hb2, out);
}